// round 15
// baseline (speedup 1.0000x reference)
#include <cuda_runtime.h>
#include <math.h>

// IN_FEATURES=128, UNITS=512, BATCH=2048, out = [x (2048*128) ; logdet (2048)]
// O(n^2) MADE inverse, warp-per-row, vectorized + L1-prefetched inner loops.
#define THREADS 512

typedef unsigned long long ull;

// ---- device scratch ----
__device__ float g_W1p[512 * 128];        // [p][j]  masked W1, hidden permuted
__device__ float g_W2q[512 * 512];        // [q][p]  masked W2 (scalar path, i<4)
__device__ float g_W2zf[256 * 512 * 2];   // [q/2][p]{q0,q1} paired columns
__device__ float g_W3zf[128 * 512 * 2];   // [o][q]{mu,sig} paired
__device__ float g_b1p[512];
__device__ float g_b2p[512];

__device__ __forceinline__ int posOf(int k) {
    int d = k % 127;
    int j = k / 127;
    return d * 4 + (d < 4 ? d : 4) + j;
}

// ---------------- prologue: mask + permute + repack ----------------
__global__ void k_transform(const float* __restrict__ W1, const float* __restrict__ b1,
                            const float* __restrict__ W2, const float* __restrict__ b2,
                            const float* __restrict__ W3,
                            const float* __restrict__ m1, const float* __restrict__ m2,
                            const float* __restrict__ m3) {
    int idx = blockIdx.x * blockDim.x + threadIdx.x;
    int stride = gridDim.x * blockDim.x;
    for (int t = idx; t < 512 * 128; t += stride) {
        int k = t >> 7, i = t & 127;
        g_W1p[posOf(k) * 128 + i] = W1[t] * m1[t];
    }
    for (int t = idx; t < 512 * 512; t += stride) {
        int m = t >> 9, k = t & 511;
        float v = W2[t] * m2[t];
        int q = posOf(m), p = posOf(k);
        g_W2q[q * 512 + p] = v;
        g_W2zf[((q >> 1) * 512 + p) * 2 + (q & 1)] = v;
    }
    for (int t = idx; t < 256 * 512; t += stride) {
        int o = t >> 9, m = t & 511;
        float v = W3[t] * m3[t];
        int q = posOf(m);
        if (o < 128) g_W3zf[(o * 512 + q) * 2]             = v;
        else         g_W3zf[((o - 128) * 512 + q) * 2 + 1] = v;
    }
    for (int t = idx; t < 512; t += stride) {
        g_b1p[posOf(t)] = b1[t];
        g_b2p[posOf(t)] = b2[t];
    }
}

// ---- packed f32x2 helpers ----
__device__ __forceinline__ ull dup2(float w) {
    ull r; asm("mov.b64 %0, {%1, %1};" : "=l"(r) : "f"(w)); return r;
}
__device__ __forceinline__ ull mk2(unsigned lo, unsigned hi) {
    ull r; asm("mov.b64 %0, {%1, %2};" : "=l"(r) : "r"(lo), "r"(hi)); return r;
}
__device__ __forceinline__ float2 u2f(ull v) {
    float2 f; asm("mov.b64 {%0, %1}, %2;" : "=f"(f.x), "=f"(f.y) : "l"(v)); return f;
}
__device__ __forceinline__ void pfma(ull& acc, ull w, ull v) {
    asm("fma.rn.f32x2 %0, %1, %2, %0;" : "+l"(acc) : "l"(w), "l"(v));
}
__device__ __forceinline__ void addp(ull& a, ull b) {
    asm("add.rn.f32x2 %0, %0, %1;" : "+l"(a) : "l"(b));
}

// smem per-row layout (floats)
#define OFF_H1 0
#define OFF_H2 512
#define OFF_X  1024
#define OFF_U  1152
#define SR     1288      // row stride (floats); SR*4 divisible by 16

// ---------------- main kernel: 128 CTAs x 16 warps, warp = row ----------------
__global__ void __launch_bounds__(THREADS, 1)
k_main(const float* __restrict__ u, const float* __restrict__ b3,
       float* __restrict__ out) {
    extern __shared__ float sm[];
    float* b3s = sm + 16 * SR;          // 256 floats
    const int tid  = threadIdx.x;
    const int lane = tid & 31;
    const int w    = tid >> 5;          // warp id == local row
    const int row0 = blockIdx.x * 16;

    float* h1 = sm + w * SR + OFF_H1;
    float* h2 = sm + w * SR + OFF_H2;
    float* xr = sm + w * SR + OFF_X;
    float* ur = sm + w * SR + OFF_U;

    // zero h1/h2/x (products past prefix use zero weights; garbage never read)
    for (int t = tid; t < 16 * 1152; t += THREADS) {
        int r = t / 1152, o = t - r * 1152;
        sm[r * SR + o] = 0.f;
    }
    for (int t = tid; t < 16 * 128; t += THREADS) {
        int r = t >> 7, c = t & 127;
        sm[r * SR + OFF_U + c] = u[(row0 + r) * 128 + c];
    }
    if (tid < 256) b3s[tid] = b3[tid];
    float ldacc = 0.f;
    __syncthreads();

    const ull* W2z = (const ull*)g_W2zf;

    for (int i = 0; i < 128; ++i) {
        const int s_i = 4 * i + (i < 4 ? i : 4);

        // ---- prefetch next step's weight rows into L1 (one warp, fire & forget) ----
        if (w == (i & 15) && i + 1 < 128) {
            int ip = i + 1;
            int s_nn = 4 * ip + (ip < 4 ? ip : 4);
            const char* w3p = (const char*)((const ull*)g_W3zf + (size_t)ip * 512);
            asm volatile("prefetch.global.L1 [%0];" :: "l"(w3p + lane * 128));
            const char* w2p = (const char*)g_W2zf + (size_t)s_nn * 2048;
            asm volatile("prefetch.global.L1 [%0];" :: "l"(w2p + lane * 128));
            asm volatile("prefetch.global.L1 [%0];" :: "l"(w2p + 4096 + lane * 128));
            const char* w1p = (const char*)(g_W1p + (size_t)s_nn * 128);
            if (lane < 16)
                asm volatile("prefetch.global.L1 [%0];" :: "l"(w1p + lane * 128));
        }

        // ---- Z: (mu_i, sigma_i); lane handles q-pair, groups of 4 passes ----
        {
            ull acc0 = 0ull, acc1 = 0ull;
            const uint4* wz4 = (const uint4*)((const ull*)g_W3zf + (size_t)i * 512);
            const int nG = (s_i + 255) >> 8;   // <= 2
            for (int g = 0; g < nG; ++g) {
                uint4 wv[4]; float2 hv[4];
#pragma unroll
                for (int b = 0; b < 4; ++b) {
                    int idx = lane + ((g * 4 + b) << 5);
                    wv[b] = __ldg(wz4 + idx);
                    hv[b] = *(const float2*)(h2 + 2 * idx);
                }
#pragma unroll
                for (int b = 0; b < 4; ++b) {
                    pfma(acc0, mk2(wv[b].x, wv[b].y), dup2(hv[b].x));
                    pfma(acc1, mk2(wv[b].z, wv[b].w), dup2(hv[b].y));
                }
            }
            addp(acc0, acc1);
#pragma unroll
            for (int off = 16; off >= 1; off >>= 1)
                addp(acc0, __shfl_xor_sync(0xffffffffu, acc0, off));
            float2 ms = u2f(acc0);
            float sg = ms.y + b3s[i + 128];
            float xv = ur[i] * __expf(sg) + (ms.x + b3s[i]);
            if (lane == 0) { xr[i] = xv; ldacc += sg; }
        }
        __syncwarp();
        if (i == 127) break;

        const int nd  = (i < 4) ? 5 : 4;
        const int s_n = s_i + nd;

        // ---- H1: new layer-1 cols; 8 lanes/col, lane = float4 of j ----
        {
            int g8 = lane >> 3, sp = lane & 7;
            int len = i + 1;
            int nG = (len + 63) >> 6;              // <= 2
            int nCols = (nd + 3) >> 2;             // 1 or 2 (uniform)
            const float4* xr4 = (const float4*)xr;
            for (int cc = 0; cc < nCols; ++cc) {
                int c  = cc * 4 + g8;
                int cA = c < nd ? c : nd - 1;
                int p  = s_i + cA;
                const float4* w1r = (const float4*)(g_W1p + p * 128);
                float a0 = 0.f, a1 = 0.f;
                for (int g = 0; g < nG; ++g) {
                    float4 wv[2], xv[2];
#pragma unroll
                    for (int b = 0; b < 2; ++b) {
                        int idx = sp + ((g * 2 + b) << 3);
                        wv[b] = __ldg(w1r + idx);
                        xv[b] = xr4[idx];
                    }
#pragma unroll
                    for (int b = 0; b < 2; ++b) {
                        a0 = fmaf(wv[b].x, xv[b].x, a0);
                        a1 = fmaf(wv[b].y, xv[b].y, a1);
                        a0 = fmaf(wv[b].z, xv[b].z, a0);
                        a1 = fmaf(wv[b].w, xv[b].w, a1);
                    }
                }
                float a = a0 + a1;
                a += __shfl_xor_sync(0xffffffffu, a, 1);
                a += __shfl_xor_sync(0xffffffffu, a, 2);
                a += __shfl_xor_sync(0xffffffffu, a, 4);
                if (sp == 0 && c < nd) h1[p] = fmaxf(g_b1p[p] + a, 0.f);
            }
        }
        __syncwarp();

        // ---- H2: new layer-2 cols ----
        if (i >= 4) {
            // q-pairs; 16 lanes/pair; lane = p-pair (uint4 weights, float2 h1)
            int h  = lane >> 4;
            int sp = lane & 15;
            const uint4* w2r = (const uint4*)(W2z + ((size_t)(s_i >> 1) + h) * 512);
            ull acc0 = 0ull, acc1 = 0ull;
            const int nG = (s_n + 127) >> 7;       // <= 4
            for (int g = 0; g < nG; ++g) {
                uint4 wv[4]; float2 hv[4];
#pragma unroll
                for (int b = 0; b < 4; ++b) {
                    int idx = sp + ((g * 4 + b) << 4);
                    wv[b] = __ldg(w2r + idx);
                    hv[b] = *(const float2*)(h1 + 2 * idx);
                }
#pragma unroll
                for (int b = 0; b < 4; ++b) {
                    pfma(acc0, mk2(wv[b].x, wv[b].y), dup2(hv[b].x));
                    pfma(acc1, mk2(wv[b].z, wv[b].w), dup2(hv[b].y));
                }
            }
            addp(acc0, acc1);
#pragma unroll
            for (int off = 8; off >= 1; off >>= 1)
                addp(acc0, __shfl_xor_sync(0xffffffffu, acc0, off));
            if (sp == 0) {
                float2 v = u2f(acc0);
                int q0 = s_i + 2 * h;
                h2[q0]     = fmaxf(g_b2p[q0] + v.x, 0.f);
                h2[q0 + 1] = fmaxf(g_b2p[q0 + 1] + v.y, 0.f);
            }
        } else {
            // scalar fallback (i<4, s_n<=20): 8 lanes/col, 3 fixed batches
            int g8 = lane >> 3, sp = lane & 7;
            int nIter = (nd + 3) >> 2;
            for (int cc = 0; cc < nIter; ++cc) {
                int c  = cc * 4 + g8;
                int cA = c < nd ? c : nd - 1;
                int q  = s_i + cA;
                const float* w2row = g_W2q + q * 512;
                float a = 0.f;
#pragma unroll
                for (int b = 0; b < 3; ++b) {
                    int p = sp + (b << 3);
                    a = fmaf(__ldg(w2row + p), h1[p], a);
                }
                a += __shfl_xor_sync(0xffffffffu, a, 1);
                a += __shfl_xor_sync(0xffffffffu, a, 2);
                a += __shfl_xor_sync(0xffffffffu, a, 4);
                if (sp == 0 && c < nd) h2[q] = fmaxf(g_b2p[q] + a, 0.f);
            }
        }
        __syncwarp();
    }

    if (lane == 0) out[2048 * 128 + row0 + w] = ldacc;

    __syncthreads();
    for (int t = tid; t < 16 * 128; t += THREADS) {
        int r = t >> 7, c = t & 127;
        out[(row0 + r) * 128 + c] = sm[r * SR + OFF_X + c];
    }
}

extern "C" void kernel_launch(void* const* d_in, const int* in_sizes, int n_in,
                              void* d_out, int out_size) {
    const float* u  = (const float*)d_in[0];
    const float* W1 = (const float*)d_in[1];
    const float* b1 = (const float*)d_in[2];
    const float* W2 = (const float*)d_in[3];
    const float* b2 = (const float*)d_in[4];
    const float* W3 = (const float*)d_in[5];
    const float* b3 = (const float*)d_in[6];
    const float* m1 = (const float*)d_in[7];
    const float* m2 = (const float*)d_in[8];
    const float* m3 = (const float*)d_in[9];
    float* out = (float*)d_out;

    const size_t smem = (size_t)(16 * SR + 256) * sizeof(float); // 83456 B
    cudaFuncSetAttribute(k_main, cudaFuncAttributeMaxDynamicSharedMemorySize, (int)smem);

    k_transform<<<256, 256>>>(W1, b1, W2, b2, W3, m1, m2, m3);
    k_main<<<128, THREADS, smem>>>(u, b3, out);
}